// round 2
// baseline (speedup 1.0000x reference)
#include <cuda_runtime.h>
#include <cstddef>

#define B 512
#define S 2048
#define V 29
#define H 128

// dec_in scratch: (B, 32) padded
__device__ float g_decin[B * 32];

__device__ __forceinline__ float fast_tanh(float x) {
    // tanh(x) = 1 - 2/(e^{2x}+1); exp2f -> MUFU.EX2 (~2 ulp), handles +/-inf saturation.
    float e = exp2f(x * 2.885390081777927f); // 2/ln(2)
    return 1.0f - __fdividef(2.0f, e + 1.0f);
}

__global__ __launch_bounds__(128, 3)
void enc_kernel(const float* __restrict__ x,
                const float* __restrict__ We_ih,
                const float* __restrict__ We_hh,
                const float* __restrict__ be_ih,
                const float* __restrict__ be_hh,
                const float* __restrict__ Wd_ih,
                const float* __restrict__ bd_ih,
                const float* __restrict__ bd_hh)
{
    const int b = blockIdx.x;
    const int i = threadIdx.x;

    __shared__ float Wih[V][H];     // transposed: Wih[k][i] = We_ih[i*V + k]
    __shared__ float hbuf[2][H];
    __shared__ float xbuf[2][32];

    // W_hh row i into registers (float4 loads)
    float w[H];
    {
        const float4* wr = (const float4*)(We_hh + (size_t)i * H);
        #pragma unroll
        for (int j4 = 0; j4 < H / 4; j4++) {
            float4 v = wr[j4];
            w[4 * j4 + 0] = v.x;
            w[4 * j4 + 1] = v.y;
            w[4 * j4 + 2] = v.z;
            w[4 * j4 + 3] = v.w;
        }
    }
    // We_ih transposed into shared
    #pragma unroll
    for (int k = 0; k < V; k++) Wih[k][i] = We_ih[(size_t)i * V + k];

    const float bias = be_ih[i] + be_hh[i];

    hbuf[0][i] = 0.0f;
    const float* xrow = x + (size_t)b * S * V;
    if (i < V) xbuf[0][i] = xrow[i];
    __syncthreads();

    #pragma unroll 1
    for (int t = 0; t < S; t++) {
        const int cur = t & 1;

        // prefetch next x slice (clamped; last-iter store is dead data, never read)
        float xn = 0.0f;
        const int tn = (t + 1 < S) ? (t + 1) : t;
        if (i < V) xn = __ldg(&xrow[(size_t)tn * V + i]);

        // input projection: acc = bias + We_ih[i,:] . x_t
        float acc = bias;
        #pragma unroll
        for (int k = 0; k < V; k++)
            acc += Wih[k][i] * xbuf[cur][k];

        // recurrence: + We_hh[i,:] . h
        float a0 = 0.f, a1 = 0.f, a2 = 0.f, a3 = 0.f;
        #pragma unroll
        for (int j = 0; j < H; j += 4) {
            float4 h4 = *(const float4*)&hbuf[cur][j];
            a0 = fmaf(w[j + 0], h4.x, a0);
            a1 = fmaf(w[j + 1], h4.y, a1);
            a2 = fmaf(w[j + 2], h4.z, a2);
            a3 = fmaf(w[j + 3], h4.w, a3);
        }
        acc += (a0 + a1) + (a2 + a3);

        float hn = fast_tanh(acc);
        hbuf[cur ^ 1][i] = hn;
        if (i < V) xbuf[cur ^ 1][i] = xn;
        __syncthreads();
    }

    // final hidden state is in hbuf[0] (S even). Compute dec_in row.
    if (i < V) {
        float acc = bd_ih[i] + bd_hh[i];
        const float* wr = Wd_ih + (size_t)i * H;
        float d0 = 0.f, d1 = 0.f, d2 = 0.f, d3 = 0.f;
        #pragma unroll
        for (int j = 0; j < H; j += 4) {
            d0 = fmaf(wr[j + 0], hbuf[0][j + 0], d0);
            d1 = fmaf(wr[j + 1], hbuf[0][j + 1], d1);
            d2 = fmaf(wr[j + 2], hbuf[0][j + 2], d2);
            d3 = fmaf(wr[j + 3], hbuf[0][j + 3], d3);
        }
        g_decin[b * 32 + i] = acc + (d0 + d1) + (d2 + d3);
    }
}

__global__ __launch_bounds__(128, 8)
void dec_kernel(const float* __restrict__ Wd_hh, float* __restrict__ out)
{
    const int warp = (blockIdx.x * blockDim.x + threadIdx.x) >> 5;
    const int lane = threadIdx.x & 31;
    if (warp >= B) return;
    const int b = warp;
    const bool act = (lane < V);

    // Wd_hh row for this lane's output element
    float w[V];
    #pragma unroll
    for (int k = 0; k < V; k++)
        w[k] = act ? Wd_hh[(size_t)lane * V + k] : 0.0f;

    const float din = act ? g_decin[b * 32 + lane] : 0.0f;

    float h = 0.0f;
    float* orow = out + (size_t)b * S * V;

    #pragma unroll 1
    for (int t = 0; t < S; t++) {
        float a0 = din, a1 = 0.f, a2 = 0.f, a3 = 0.f;
        #pragma unroll
        for (int k = 0; k < V; k++) {
            float hk = __shfl_sync(0xffffffffu, h, k);
            if ((k & 3) == 0)      a0 = fmaf(w[k], hk, a0);
            else if ((k & 3) == 1) a1 = fmaf(w[k], hk, a1);
            else if ((k & 3) == 2) a2 = fmaf(w[k], hk, a2);
            else                   a3 = fmaf(w[k], hk, a3);
        }
        h = fast_tanh((a0 + a1) + (a2 + a3));
        if (act) orow[(size_t)t * V + lane] = h;
    }
}

extern "C" void kernel_launch(void* const* d_in, const int* in_sizes, int n_in,
                              void* d_out, int out_size)
{
    const float* x     = (const float*)d_in[0];
    const float* We_ih = (const float*)d_in[1];
    const float* We_hh = (const float*)d_in[2];
    const float* be_ih = (const float*)d_in[3];
    const float* be_hh = (const float*)d_in[4];
    const float* Wd_ih = (const float*)d_in[5];
    const float* Wd_hh = (const float*)d_in[6];
    const float* bd_ih = (const float*)d_in[7];
    const float* bd_hh = (const float*)d_in[8];
    float* out = (float*)d_out;

    enc_kernel<<<B, 128>>>(x, We_ih, We_hh, be_ih, be_hh, Wd_ih, bd_ih, bd_hh);
    dec_kernel<<<(B * 32) / 128, 128>>>(Wd_hh, out);
}